// round 2
// baseline (speedup 1.0000x reference)
#include <cuda_runtime.h>
#include <math.h>

#define Bb   4
#define Nn   2048
#define FEAT 512
#define HIDD 512
#define Hh   8
#define HD   64
#define ROWS (Bb*Nn)          // 8192
#define BH   (Bb*Hh)          // 32

// ---------------- scratch (static device arrays; no cudaMalloc) ----------------
__device__ float g_qkv[(size_t)ROWS*3*HIDD];
__device__ float g_q[(size_t)ROWS*HIDD];      // [BH, N, HD], pre-scaled by 1/8
__device__ float g_k[(size_t)ROWS*HIDD];      // [BH, N, HD]
__device__ float g_v[(size_t)ROWS*HIDD];      // [BH, N, HD]
__device__ float g_o[(size_t)ROWS*HIDD];      // attention out, [B,N,HID]
__device__ float g_msg[(size_t)ROWS*HIDD];
__device__ float g_h[(size_t)ROWS*2*FEAT];
__device__ float g_g[(size_t)ROWS*2*FEAT];

// ---------------- generic NN SGEMM: C = [A|A2] @ B + bias (+resid) ----------------
// 64x64 tile, K-tile 16, 256 threads, 4x4 microtile.
__global__ __launch_bounds__(256) void sgemm_nn(
    const float* __restrict__ A,  int lda,
    const float* __restrict__ A2, int lda2, int ksplit,
    const float* __restrict__ Bm, int ldb,
    const float* __restrict__ bias,
    const float* __restrict__ resid, int ldr,
    float* __restrict__ C, int ldc,
    int M, int N, int K)
{
    __shared__ float As[16*68];     // As[kk*68 + row], padded pitch
    __shared__ float Bs[16*64];     // Bs[kk*64 + col]

    const int t  = threadIdx.x;
    const int tx = t & 15;
    const int ty = t >> 4;
    const int rb = blockIdx.y * 64;
    const int cb = blockIdx.x * 64;

    const int arow = t >> 2;          // 0..63
    const int ak4  = (t & 3) << 2;    // 0,4,8,12
    const int bkk  = t >> 4;          // 0..15
    const int bc4  = (t & 15) << 2;   // 0..60

    float acc[4][4] = {};

    for (int kb = 0; kb < K; kb += 16) {
        int kg = kb + ak4;
        const float* asrc;
        if (A2 != nullptr && kg >= ksplit)
            asrc = A2 + (size_t)(rb + arow) * lda2 + (kg - ksplit);
        else
            asrc = A  + (size_t)(rb + arow) * lda  + kg;
        float4 av = *(const float4*)asrc;
        As[(ak4+0)*68 + arow] = av.x;
        As[(ak4+1)*68 + arow] = av.y;
        As[(ak4+2)*68 + arow] = av.z;
        As[(ak4+3)*68 + arow] = av.w;
        float4 bv = *(const float4*)(Bm + (size_t)(kb + bkk) * ldb + cb + bc4);
        *(float4*)&Bs[bkk*64 + bc4] = bv;
        __syncthreads();

        #pragma unroll
        for (int kk = 0; kk < 16; ++kk) {
            float4 a = *(const float4*)(As + kk*68 + (ty<<2));
            float4 b = *(const float4*)(Bs + kk*64 + (tx<<2));
            float ar[4] = {a.x, a.y, a.z, a.w};
            float br[4] = {b.x, b.y, b.z, b.w};
            #pragma unroll
            for (int i = 0; i < 4; ++i)
                #pragma unroll
                for (int j = 0; j < 4; ++j)
                    acc[i][j] = fmaf(ar[i], br[j], acc[i][j]);
        }
        __syncthreads();
    }

    const int c0 = cb + (tx << 2);
    float4 bz = *(const float4*)(bias + c0);
    #pragma unroll
    for (int i = 0; i < 4; ++i) {
        int r = rb + (ty << 2) + i;
        float4 o;
        o.x = acc[i][0] + bz.x;
        o.y = acc[i][1] + bz.y;
        o.z = acc[i][2] + bz.z;
        o.w = acc[i][3] + bz.w;
        if (resid != nullptr) {
            float4 rv = *(const float4*)(resid + (size_t)r * ldr + c0);
            o.x += rv.x; o.y += rv.y; o.z += rv.z; o.w += rv.w;
        }
        *(float4*)&C[(size_t)r * ldc + c0] = o;
    }
}

// ---------------- RoPE + qkv split into [BH,N,HD]; q pre-scaled by 1/8 ----------------
__global__ __launch_bounds__(256) void rope_kernel(
    const float* __restrict__ qkv, const float* __restrict__ enc,
    float* __restrict__ qb, float* __restrict__ kb, float* __restrict__ vb)
{
    int idx = blockIdx.x * blockDim.x + threadIdx.x;    // over B*N*H*HD/2
    int p  = idx & (HD/2 - 1);           // pair index 0..31
    int tmp = idx >> 5;                  // /32
    int h  = tmp & (Hh - 1);
    tmp >>= 3;                           // /8
    int n  = tmp & (Nn - 1);
    int b  = tmp >> 11;                  // /2048

    size_t row  = (size_t)b * Nn + n;
    size_t base = row * (3*HIDD) + h * (HD*3) + (2*p)*3;
    float q0 = qkv[base+0], k0 = qkv[base+1], v0 = qkv[base+2];
    float q1 = qkv[base+3], k1 = qkv[base+4], v1 = qkv[base+5];

    size_t eb = row * HD + 2*p;
    const size_t ESTR = (size_t)Bb * Nn * HD;
    float f00 = enc[eb],        f01 = enc[eb+1];
    float f10 = enc[ESTR+eb],   f11 = enc[ESTR+eb+1];

    float qo0 = (q0*f00 - q1*f10) * 0.125f;
    float qo1 = (q1*f01 + q0*f11) * 0.125f;
    float ko0 = k0*f00 - k1*f10;
    float ko1 = k1*f01 + k0*f11;

    size_t ob = (((size_t)b*Hh + h) * Nn + n) * HD + 2*p;
    qb[ob]   = qo0; qb[ob+1] = qo1;
    kb[ob]   = ko0; kb[ob+1] = ko1;
    vb[ob]   = v0;  vb[ob+1] = v1;
}

// ---------------- fused flash attention: O = softmax(QK^T)V ----------------
// One CTA: 64 query rows x full HD=64 of one (b,h). KV tiles of 64.
// Thread (tx,ty): rows ty*4+i, cols tx*4+j of the 64x64 S/P/O tiles.
// smem: Qs [d][r] (Q^T), KP [d][c] for K^T then reused as [r][k] for P, Vs [k][d].
__global__ __launch_bounds__(256) void flash_kernel(
    const float* __restrict__ Q, const float* __restrict__ K,
    const float* __restrict__ V, float* __restrict__ O)
{
    __shared__ float Qs[64*64];
    __shared__ float KP[64*64];
    __shared__ float Vs[64*64];

    const int bh = blockIdx.y;
    const int b  = bh >> 3;
    const int h  = bh & 7;
    const float* Qb = Q + (size_t)bh * Nn * HD;
    const float* Kb = K + (size_t)bh * Nn * HD;
    const float* Vb = V + (size_t)bh * Nn * HD;

    const int t    = threadIdx.x;
    const int tx   = t & 15;
    const int ty   = t >> 4;
    const int lrow = t >> 2;            // 0..63
    const int lk4  = (t & 3) << 2;      // 0,4,8,12
    const int q0r  = blockIdx.x * 64;

    // load Q tile transposed: Qs[d*64 + r]
    #pragma unroll
    for (int dd = 0; dd < 64; dd += 16) {
        float4 qv = *(const float4*)(Qb + (size_t)(q0r + lrow) * HD + dd + lk4);
        Qs[(dd+lk4+0)*64 + lrow] = qv.x;
        Qs[(dd+lk4+1)*64 + lrow] = qv.y;
        Qs[(dd+lk4+2)*64 + lrow] = qv.z;
        Qs[(dd+lk4+3)*64 + lrow] = qv.w;
    }

    float acc_o[4][4] = {};
    float m[4] = {-1e30f, -1e30f, -1e30f, -1e30f};
    float l[4] = {};

    for (int j0 = 0; j0 < Nn; j0 += 64) {
        __syncthreads();   // prior PV reads of KP/Vs complete
        // load K tile transposed: KP[d*64 + c]; V tile direct: Vs[k*64 + d]
        #pragma unroll
        for (int dd = 0; dd < 64; dd += 16) {
            float4 kv = *(const float4*)(Kb + (size_t)(j0 + lrow) * HD + dd + lk4);
            KP[(dd+lk4+0)*64 + lrow] = kv.x;
            KP[(dd+lk4+1)*64 + lrow] = kv.y;
            KP[(dd+lk4+2)*64 + lrow] = kv.z;
            KP[(dd+lk4+3)*64 + lrow] = kv.w;
            *(float4*)&Vs[lrow*64 + dd + lk4] =
                *(const float4*)(Vb + (size_t)(j0 + lrow) * HD + dd + lk4);
        }
        __syncthreads();

        // S = (Q/8) @ K^T
        float s[4][4] = {};
        #pragma unroll 16
        for (int d = 0; d < 64; ++d) {
            float4 a = *(const float4*)(Qs + d*64 + (ty<<2));
            float4 bq = *(const float4*)(KP + d*64 + (tx<<2));
            float ar[4] = {a.x, a.y, a.z, a.w};
            float br[4] = {bq.x, bq.y, bq.z, bq.w};
            #pragma unroll
            for (int i = 0; i < 4; ++i)
                #pragma unroll
                for (int j = 0; j < 4; ++j)
                    s[i][j] = fmaf(ar[i], br[j], s[i][j]);
        }

        // online softmax per row (reduce across the 16 tx lanes)
        float p[4][4];
        #pragma unroll
        for (int i = 0; i < 4; ++i) {
            float tm = fmaxf(fmaxf(s[i][0], s[i][1]), fmaxf(s[i][2], s[i][3]));
            #pragma unroll
            for (int msk = 1; msk < 16; msk <<= 1)
                tm = fmaxf(tm, __shfl_xor_sync(0xffffffffu, tm, msk));
            float mn = fmaxf(m[i], tm);
            float alpha = __expf(m[i] - mn);
            m[i] = mn;
            float rs = 0.f;
            #pragma unroll
            for (int j = 0; j < 4; ++j) {
                p[i][j] = __expf(s[i][j] - mn);
                rs += p[i][j];
            }
            #pragma unroll
            for (int msk = 1; msk < 16; msk <<= 1)
                rs += __shfl_xor_sync(0xffffffffu, rs, msk);
            l[i] = l[i] * alpha + rs;
            #pragma unroll
            for (int j = 0; j < 4; ++j)
                acc_o[i][j] *= alpha;
        }

        __syncthreads();   // S-phase reads of KP complete
        // store P into KP as [r][k]
        #pragma unroll
        for (int i = 0; i < 4; ++i)
            *(float4*)&KP[((ty<<2)+i)*64 + (tx<<2)] =
                make_float4(p[i][0], p[i][1], p[i][2], p[i][3]);
        __syncthreads();

        // O += P @ V
        #pragma unroll 16
        for (int k = 0; k < 64; ++k) {
            float4 bv = *(const float4*)(Vs + k*64 + (tx<<2));
            float br[4] = {bv.x, bv.y, bv.z, bv.w};
            #pragma unroll
            for (int i = 0; i < 4; ++i) {
                float a = KP[((ty<<2)+i)*64 + k];   // broadcast across tx
                #pragma unroll
                for (int j = 0; j < 4; ++j)
                    acc_o[i][j] = fmaf(a, br[j], acc_o[i][j]);
            }
        }
    }

    // write O tile to [B,N,HID] with head offset
    #pragma unroll
    for (int i = 0; i < 4; ++i) {
        float inv = 1.0f / l[i];
        int n = q0r + (ty<<2) + i;
        float4 o;
        o.x = acc_o[i][0] * inv;
        o.y = acc_o[i][1] * inv;
        o.z = acc_o[i][2] * inv;
        o.w = acc_o[i][3] * inv;
        *(float4*)&O[((size_t)b * Nn + n) * HIDD + h * HD + (tx<<2)] = o;
    }
}

// ---------------- LayerNorm + exact GELU over rows of 1024 ----------------
__global__ __launch_bounds__(256) void ln_gelu_kernel(
    const float* __restrict__ H, const float* __restrict__ g,
    const float* __restrict__ bta, float* __restrict__ out)
{
    __shared__ float red[256];
    const float* p = H + (size_t)blockIdx.x * (2*FEAT);
    int t = threadIdx.x;
    float4 v = ((const float4*)p)[t];

    float s = v.x + v.y + v.z + v.w;
    red[t] = s; __syncthreads();
    for (int ss = 128; ss > 0; ss >>= 1) {
        if (t < ss) red[t] += red[t+ss];
        __syncthreads();
    }
    float mu = red[0] * (1.0f / (2*FEAT));
    __syncthreads();

    float d0 = v.x - mu, d1 = v.y - mu, d2 = v.z - mu, d3 = v.w - mu;
    red[t] = d0*d0 + d1*d1 + d2*d2 + d3*d3; __syncthreads();
    for (int ss = 128; ss > 0; ss >>= 1) {
        if (t < ss) red[t] += red[t+ss];
        __syncthreads();
    }
    float var = red[0] * (1.0f / (2*FEAT));
    float rs = rsqrtf(var + 1e-5f);

    int c = t << 2;
    float4 gv = *(const float4*)(g + c);
    float4 bv = *(const float4*)(bta + c);
    float y0 = d0 * rs * gv.x + bv.x;
    float y1 = d1 * rs * gv.y + bv.y;
    float y2 = d2 * rs * gv.z + bv.z;
    float y3 = d3 * rs * gv.w + bv.w;

    const float IS2 = 0.70710678118654752f;
    float4 o;
    o.x = 0.5f * y0 * (1.0f + erff(y0 * IS2));
    o.y = 0.5f * y1 * (1.0f + erff(y1 * IS2));
    o.z = 0.5f * y2 * (1.0f + erff(y2 * IS2));
    o.w = 0.5f * y3 * (1.0f + erff(y3 * IS2));
    ((float4*)(out + (size_t)blockIdx.x * (2*FEAT)))[t] = o;
}

// ---------------- host-side orchestration ----------------
static void run_block(const float* x, const float* enc,
                      const float* Wqkv, const float* bqkv,
                      const float* Wproj, const float* bproj,
                      const float* W1, const float* b1,
                      const float* ln_g, const float* ln_b,
                      const float* W2, const float* b2,
                      float* qkv, float* q, float* k, float* v,
                      float* o, float* msg, float* hh, float* gg,
                      float* outp)
{
    // qkv = x @ Wqkv + bqkv   [8192,512]@[512,1536]
    sgemm_nn<<<dim3(3*HIDD/64, ROWS/64), 256>>>(
        x, FEAT, nullptr, 0, 1<<30, Wqkv, 3*HIDD, bqkv, nullptr, 0,
        qkv, 3*HIDD, ROWS, 3*HIDD, FEAT);

    // rope + split (+ q prescale)
    rope_kernel<<<(Bb*Nn*Hh*(HD/2))/256, 256>>>(qkv, enc, q, k, v);

    // fused attention
    flash_kernel<<<dim3(Nn/64, BH), 256>>>(q, k, v, o);

    // message = O @ Wproj + bproj
    sgemm_nn<<<dim3(HIDD/64, ROWS/64), 256>>>(
        o, HIDD, nullptr, 0, 1<<30, Wproj, HIDD, bproj, nullptr, 0,
        msg, HIDD, ROWS, HIDD, HIDD);

    // h = concat(x, message) @ W1 + b1   [8192,1024]@[1024,1024]
    sgemm_nn<<<dim3(2*FEAT/64, ROWS/64), 256>>>(
        x, FEAT, msg, HIDD, FEAT, W1, 2*FEAT, b1, nullptr, 0,
        hh, 2*FEAT, ROWS, 2*FEAT, FEAT + HIDD);

    // LN + gelu
    ln_gelu_kernel<<<ROWS, 256>>>(hh, ln_g, ln_b, gg);

    // out = x + g @ W2 + b2   [8192,1024]@[1024,512]
    sgemm_nn<<<dim3(FEAT/64, ROWS/64), 256>>>(
        gg, 2*FEAT, nullptr, 0, 1<<30, W2, FEAT, b2, x, FEAT,
        outp, FEAT, ROWS, FEAT, 2*FEAT);
}

extern "C" void kernel_launch(void* const* d_in, const int* in_sizes, int n_in,
                              void* d_out, int out_size)
{
    const float* x0    = (const float*)d_in[0];
    const float* x1    = (const float*)d_in[1];
    const float* enc0  = (const float*)d_in[2];
    const float* enc1  = (const float*)d_in[3];
    const float* Wqkv  = (const float*)d_in[4];
    const float* bqkv  = (const float*)d_in[5];
    const float* Wproj = (const float*)d_in[6];
    const float* bproj = (const float*)d_in[7];
    const float* W1    = (const float*)d_in[8];
    const float* b1    = (const float*)d_in[9];
    const float* ln_g  = (const float*)d_in[10];
    const float* ln_b  = (const float*)d_in[11];
    const float* W2    = (const float*)d_in[12];
    const float* b2    = (const float*)d_in[13];
    float* out = (float*)d_out;

    float *qkv, *q, *k, *v, *o, *msg, *hh, *gg;
    cudaGetSymbolAddress((void**)&qkv, g_qkv);
    cudaGetSymbolAddress((void**)&q,   g_q);
    cudaGetSymbolAddress((void**)&k,   g_k);
    cudaGetSymbolAddress((void**)&v,   g_v);
    cudaGetSymbolAddress((void**)&o,   g_o);
    cudaGetSymbolAddress((void**)&msg, g_msg);
    cudaGetSymbolAddress((void**)&hh,  g_h);
    cudaGetSymbolAddress((void**)&gg,  g_g);

    run_block(x0, enc0, Wqkv, bqkv, Wproj, bproj, W1, b1, ln_g, ln_b, W2, b2,
              qkv, q, k, v, o, msg, hh, gg, out);
    run_block(x1, enc1, Wqkv, bqkv, Wproj, bproj, W1, b1, ln_g, ln_b, W2, b2,
              qkv, q, k, v, o, msg, hh, gg, out + (size_t)ROWS*FEAT);
}

// round 3
// speedup vs baseline: 2.7768x; 2.7768x over previous
#include <cuda_runtime.h>
#include <math.h>
#include <stdint.h>

#define Bb   4
#define Nn   2048
#define FEAT 512
#define HIDD 512
#define Hh   8
#define HD   64
#define ROWS (Bb*Nn)          // 8192
#define BH   (Bb*Hh)          // 32

// ---------------- scratch (static device arrays; no cudaMalloc) ----------------
__device__ float g_qkv[(size_t)ROWS*3*HIDD];
__device__ float g_q[(size_t)ROWS*HIDD];      // [BH,N,HD], tf32-rounded, pre-scaled 1/8
__device__ float g_k[(size_t)ROWS*HIDD];      // [BH,N,HD], tf32-rounded
__device__ float g_v[(size_t)ROWS*HIDD];      // [BH,N,HD], tf32-rounded
__device__ float g_o[(size_t)ROWS*HIDD];      // attention out, [B,N,HID]
__device__ float g_msg[(size_t)ROWS*HIDD];
__device__ float g_h[(size_t)ROWS*2*FEAT];
__device__ float g_g[(size_t)ROWS*2*FEAT];

// ---------------- tf32 helpers ----------------
__device__ __forceinline__ uint32_t f2tf(float f) {
    uint32_t u;
    asm("cvt.rna.tf32.f32 %0, %1;" : "=r"(u) : "f"(f));
    return u;
}

__device__ __forceinline__ void mma_tf32(float* d,
    uint32_t a0, uint32_t a1, uint32_t a2, uint32_t a3,
    uint32_t b0, uint32_t b1)
{
    asm volatile(
        "mma.sync.aligned.m16n8k8.row.col.f32.tf32.tf32.f32 "
        "{%0,%1,%2,%3},{%4,%5,%6,%7},{%8,%9},{%0,%1,%2,%3};"
        : "+f"(d[0]), "+f"(d[1]), "+f"(d[2]), "+f"(d[3])
        : "r"(a0), "r"(a1), "r"(a2), "r"(a3), "r"(b0), "r"(b1));
}

// ---------------- tf32 GEMM: C = [A|A2] @ B + bias (+resid) ----------------
// 128x128 block tile, K-tile 16, 256 threads (8 warps, 4x2), warp tile 32x64.
// A smem [row][k] pitch 20 (banks 4r+c distinct), B smem [k][n] pitch 136 (banks 8k+n).
__global__ __launch_bounds__(256) void gemm_tf32(
    const float* __restrict__ A,  int lda,
    const float* __restrict__ A2, int lda2, int ksplit,
    const float* __restrict__ Bm, int ldb,
    const float* __restrict__ bias,
    const float* __restrict__ resid, int ldr,
    float* __restrict__ C, int ldc, int K)
{
    __shared__ uint32_t As[2][128*20];
    __shared__ uint32_t Bs[2][16*136];

    const int t    = threadIdx.x;
    const int lane = t & 31;
    const int warp = t >> 5;
    const int wm   = warp & 3;       // 0..3
    const int wn   = warp >> 2;      // 0..1
    const int rb   = blockIdx.y * 128;
    const int cb   = blockIdx.x * 128;

    const int arow = t >> 1;          // 0..127
    const int ah   = (t & 1) * 8;     // 0 or 8
    const int bk   = t >> 4;          // 0..15
    const int bn   = (t & 15) * 4;    // 0..60

    const int gid  = lane >> 2;       // 0..7
    const int tig  = lane & 3;        // 0..3

    float acc[2][8][4] = {};

    float4 av0, av1, bv0, bv1;
    // prologue load tile 0
    {
        int kg = 0 + ah;
        const float* asrc = (A2 && kg >= ksplit)
            ? A2 + (size_t)(rb + arow) * lda2 + (kg - ksplit)
            : A  + (size_t)(rb + arow) * lda  + kg;
        av0 = *(const float4*)asrc;
        av1 = *(const float4*)(asrc + 4);
        const float* bsrc = Bm + (size_t)bk * ldb + cb + bn;
        bv0 = *(const float4*)bsrc;
        bv1 = *(const float4*)(bsrc + 64);
    }
    {
        uint32_t* ap = &As[0][arow*20 + ah];
        ap[0]=f2tf(av0.x); ap[1]=f2tf(av0.y); ap[2]=f2tf(av0.z); ap[3]=f2tf(av0.w);
        ap[4]=f2tf(av1.x); ap[5]=f2tf(av1.y); ap[6]=f2tf(av1.z); ap[7]=f2tf(av1.w);
        uint32_t* bp = &Bs[0][bk*136 + bn];
        bp[0]=f2tf(bv0.x); bp[1]=f2tf(bv0.y); bp[2]=f2tf(bv0.z); bp[3]=f2tf(bv0.w);
        bp += 64;
        bp[0]=f2tf(bv1.x); bp[1]=f2tf(bv1.y); bp[2]=f2tf(bv1.z); bp[3]=f2tf(bv1.w);
    }
    __syncthreads();

    const int nk = K >> 4;
    for (int kt = 0; kt < nk; ++kt) {
        const int cur = kt & 1;
        if (kt + 1 < nk) {
            int kb = (kt + 1) << 4;
            int kg = kb + ah;
            const float* asrc = (A2 && kg >= ksplit)
                ? A2 + (size_t)(rb + arow) * lda2 + (kg - ksplit)
                : A  + (size_t)(rb + arow) * lda  + kg;
            av0 = *(const float4*)asrc;
            av1 = *(const float4*)(asrc + 4);
            const float* bsrc = Bm + (size_t)(kb + bk) * ldb + cb + bn;
            bv0 = *(const float4*)bsrc;
            bv1 = *(const float4*)(bsrc + 64);
        }

        const uint32_t* Ac = As[cur];
        const uint32_t* Bc = Bs[cur];
        #pragma unroll
        for (int ks = 0; ks < 2; ++ks) {
            uint32_t af[2][4];
            #pragma unroll
            for (int mt = 0; mt < 2; ++mt) {
                int r = wm*32 + mt*16 + gid;
                int c = ks*8 + tig;
                af[mt][0] = Ac[r*20 + c];
                af[mt][1] = Ac[(r+8)*20 + c];
                af[mt][2] = Ac[r*20 + c + 4];
                af[mt][3] = Ac[(r+8)*20 + c + 4];
            }
            #pragma unroll
            for (int nt = 0; nt < 8; ++nt) {
                int n = wn*64 + nt*8 + gid;
                int k = ks*8 + tig;
                uint32_t b0 = Bc[k*136 + n];
                uint32_t b1 = Bc[(k+4)*136 + n];
                mma_tf32(acc[0][nt], af[0][0], af[0][1], af[0][2], af[0][3], b0, b1);
                mma_tf32(acc[1][nt], af[1][0], af[1][1], af[1][2], af[1][3], b0, b1);
            }
        }

        if (kt + 1 < nk) {
            const int nxt = (kt + 1) & 1;
            uint32_t* ap = &As[nxt][arow*20 + ah];
            ap[0]=f2tf(av0.x); ap[1]=f2tf(av0.y); ap[2]=f2tf(av0.z); ap[3]=f2tf(av0.w);
            ap[4]=f2tf(av1.x); ap[5]=f2tf(av1.y); ap[6]=f2tf(av1.z); ap[7]=f2tf(av1.w);
            uint32_t* bp = &Bs[nxt][bk*136 + bn];
            bp[0]=f2tf(bv0.x); bp[1]=f2tf(bv0.y); bp[2]=f2tf(bv0.z); bp[3]=f2tf(bv0.w);
            bp += 64;
            bp[0]=f2tf(bv1.x); bp[1]=f2tf(bv1.y); bp[2]=f2tf(bv1.z); bp[3]=f2tf(bv1.w);
        }
        __syncthreads();
    }

    // epilogue
    #pragma unroll
    for (int mt = 0; mt < 2; ++mt) {
        #pragma unroll
        for (int nt = 0; nt < 8; ++nt) {
            int row0 = rb + wm*32 + mt*16 + gid;
            int col  = cb + wn*64 + nt*8 + 2*tig;
            float2 bz = *(const float2*)(bias + col);
            float2 o0, o1;
            o0.x = acc[mt][nt][0] + bz.x;
            o0.y = acc[mt][nt][1] + bz.y;
            o1.x = acc[mt][nt][2] + bz.x;
            o1.y = acc[mt][nt][3] + bz.y;
            if (resid != nullptr) {
                float2 r0 = *(const float2*)(resid + (size_t)row0 * ldr + col);
                float2 r1 = *(const float2*)(resid + (size_t)(row0+8) * ldr + col);
                o0.x += r0.x; o0.y += r0.y;
                o1.x += r1.x; o1.y += r1.y;
            }
            *(float2*)(C + (size_t)row0 * ldc + col)     = o0;
            *(float2*)(C + (size_t)(row0+8) * ldc + col) = o1;
        }
    }
}

// ---------------- RoPE + split; outputs tf32-rounded; q pre-scaled 1/8 ----------------
__global__ __launch_bounds__(256) void rope_kernel(
    const float* __restrict__ qkv, const float* __restrict__ enc,
    float* __restrict__ qb, float* __restrict__ kb, float* __restrict__ vb)
{
    int idx = blockIdx.x * blockDim.x + threadIdx.x;
    int p  = idx & (HD/2 - 1);
    int tmp = idx >> 5;
    int h  = tmp & (Hh - 1);
    tmp >>= 3;
    int n  = tmp & (Nn - 1);
    int b  = tmp >> 11;

    size_t row  = (size_t)b * Nn + n;
    size_t base = row * (3*HIDD) + h * (HD*3) + (2*p)*3;
    float q0 = qkv[base+0], k0 = qkv[base+1], v0 = qkv[base+2];
    float q1 = qkv[base+3], k1 = qkv[base+4], v1 = qkv[base+5];

    size_t eb = row * HD + 2*p;
    const size_t ESTR = (size_t)Bb * Nn * HD;
    float f00 = enc[eb],      f01 = enc[eb+1];
    float f10 = enc[ESTR+eb], f11 = enc[ESTR+eb+1];

    float qo0 = (q0*f00 - q1*f10) * 0.125f;
    float qo1 = (q1*f01 + q0*f11) * 0.125f;
    float ko0 = k0*f00 - k1*f10;
    float ko1 = k1*f01 + k0*f11;

    size_t ob = (((size_t)b*Hh + h) * Nn + n) * HD + 2*p;
    qb[ob]   = __uint_as_float(f2tf(qo0));
    qb[ob+1] = __uint_as_float(f2tf(qo1));
    kb[ob]   = __uint_as_float(f2tf(ko0));
    kb[ob+1] = __uint_as_float(f2tf(ko1));
    vb[ob]   = __uint_as_float(f2tf(v0));
    vb[ob+1] = __uint_as_float(f2tf(v1));
}

// ---------------- tf32 flash attention ----------------
// CTA: 128 q-rows x HD=64 of one (b,h); kv tiles of 64; 8 warps, warp owns m16 rows.
// smem (dynamic, uint32): Q[128][68], K[64][68], V[64][72], P[128][68].
#define QOFF 0
#define KOFF (128*68)
#define VOFF (KOFF + 64*68)
#define POFF (VOFF + 64*72)
#define FLASH_SMEM_U32 (POFF + 128*68)

__global__ __launch_bounds__(256) void flash_tf32(
    const float* __restrict__ Q, const float* __restrict__ K,
    const float* __restrict__ V, float* __restrict__ O)
{
    extern __shared__ uint32_t smu[];
    uint32_t* Qs = smu + QOFF;
    uint32_t* Ks = smu + KOFF;
    uint32_t* Vs = smu + VOFF;
    uint32_t* Ps = smu + POFF;

    const int bh = blockIdx.y;
    const int b  = bh >> 3;
    const int h  = bh & 7;
    const uint32_t* Qg = (const uint32_t*)(Q + (size_t)bh * Nn * HD);
    const uint32_t* Kg = (const uint32_t*)(K + (size_t)bh * Nn * HD);
    const uint32_t* Vg = (const uint32_t*)(V + (size_t)bh * Nn * HD);

    const int t    = threadIdx.x;
    const int lane = t & 31;
    const int warp = t >> 5;           // 0..7, owns rows [warp*16, +16)
    const int gid  = lane >> 2;        // 0..7
    const int tig  = lane & 3;         // 0..3
    const int q0r  = blockIdx.x * 128;

    // stage Q tile (already tf32 bits)
    #pragma unroll
    for (int i = 0; i < 8; ++i) {
        int idx = t + 256*i;
        int row = idx >> 4, dq = (idx & 15) << 2;
        *(uint4*)&Qs[row*68 + dq] = *(const uint4*)&Qg[(size_t)(q0r + row)*HD + dq];
    }

    float accO[8][4] = {};
    float mrow[2] = {-1e30f, -1e30f};
    float lrow[2] = {0.f, 0.f};

    for (int j0 = 0; j0 < Nn; j0 += 64) {
        __syncthreads();
        #pragma unroll
        for (int i = 0; i < 4; ++i) {
            int idx = t + 256*i;
            int row = idx >> 4, dq = (idx & 15) << 2;
            *(uint4*)&Ks[row*68 + dq] = *(const uint4*)&Kg[(size_t)(j0 + row)*HD + dq];
            *(uint4*)&Vs[row*72 + dq] = *(const uint4*)&Vg[(size_t)(j0 + row)*HD + dq];
        }
        __syncthreads();

        // S = Q @ K^T (q pre-scaled)
        float s[8][4] = {};
        #pragma unroll
        for (int ks = 0; ks < 8; ++ks) {
            int r = warp*16 + gid;
            int c = ks*8 + tig;
            uint32_t a0 = Qs[r*68 + c];
            uint32_t a1 = Qs[(r+8)*68 + c];
            uint32_t a2 = Qs[r*68 + c + 4];
            uint32_t a3 = Qs[(r+8)*68 + c + 4];
            #pragma unroll
            for (int nt = 0; nt < 8; ++nt) {
                int n = nt*8 + gid;
                int k = ks*8 + tig;
                uint32_t b0 = Ks[n*68 + k];
                uint32_t b1 = Ks[n*68 + k + 4];
                mma_tf32(s[nt], a0, a1, a2, a3, b0, b1);
            }
        }

        // online softmax per row-group
        #pragma unroll
        for (int g = 0; g < 2; ++g) {
            float tm = -1e30f;
            #pragma unroll
            for (int nt = 0; nt < 8; ++nt)
                tm = fmaxf(tm, fmaxf(s[nt][2*g], s[nt][2*g+1]));
            tm = fmaxf(tm, __shfl_xor_sync(0xffffffffu, tm, 1));
            tm = fmaxf(tm, __shfl_xor_sync(0xffffffffu, tm, 2));
            float mn = fmaxf(mrow[g], tm);
            float alpha = __expf(mrow[g] - mn);
            mrow[g] = mn;
            float rs = 0.f;
            #pragma unroll
            for (int nt = 0; nt < 8; ++nt) {
                float p0 = __expf(s[nt][2*g]   - mn);
                float p1 = __expf(s[nt][2*g+1] - mn);
                s[nt][2*g] = p0; s[nt][2*g+1] = p1;
                rs += p0 + p1;
            }
            rs += __shfl_xor_sync(0xffffffffu, rs, 1);
            rs += __shfl_xor_sync(0xffffffffu, rs, 2);
            lrow[g] = lrow[g]*alpha + rs;
            #pragma unroll
            for (int nt = 0; nt < 8; ++nt) {
                accO[nt][2*g]   *= alpha;
                accO[nt][2*g+1] *= alpha;
            }
        }

        // store P (tf32) to per-warp smem region
        {
            int r0 = warp*16 + gid;
            #pragma unroll
            for (int nt = 0; nt < 8; ++nt) {
                int pc = nt*8 + 2*tig;
                Ps[r0*68 + pc]       = f2tf(s[nt][0]);
                Ps[r0*68 + pc + 1]   = f2tf(s[nt][1]);
                Ps[(r0+8)*68 + pc]     = f2tf(s[nt][2]);
                Ps[(r0+8)*68 + pc + 1] = f2tf(s[nt][3]);
            }
        }
        __syncwarp();

        // O += P @ V
        #pragma unroll
        for (int ks = 0; ks < 8; ++ks) {
            int r = warp*16 + gid;
            int c = ks*8 + tig;
            uint32_t a0 = Ps[r*68 + c];
            uint32_t a1 = Ps[(r+8)*68 + c];
            uint32_t a2 = Ps[r*68 + c + 4];
            uint32_t a3 = Ps[(r+8)*68 + c + 4];
            #pragma unroll
            for (int nt = 0; nt < 8; ++nt) {
                int n = nt*8 + gid;
                int k = ks*8 + tig;
                uint32_t b0 = Vs[k*72 + n];
                uint32_t b1 = Vs[(k+4)*72 + n];
                mma_tf32(accO[nt], a0, a1, a2, a3, b0, b1);
            }
        }
    }

    // epilogue
    #pragma unroll
    for (int g = 0; g < 2; ++g) {
        float inv = 1.0f / lrow[g];
        int n = q0r + warp*16 + gid + 8*g;
        #pragma unroll
        for (int nt = 0; nt < 8; ++nt) {
            int col = h*64 + nt*8 + 2*tig;
            float2 o;
            o.x = accO[nt][2*g]   * inv;
            o.y = accO[nt][2*g+1] * inv;
            *(float2*)&O[((size_t)b * Nn + n) * HIDD + col] = o;
        }
    }
}

// ---------------- LayerNorm + exact GELU over rows of 1024 ----------------
__global__ __launch_bounds__(256) void ln_gelu_kernel(
    const float* __restrict__ H, const float* __restrict__ g,
    const float* __restrict__ bta, float* __restrict__ out)
{
    __shared__ float red[256];
    const float* p = H + (size_t)blockIdx.x * (2*FEAT);
    int t = threadIdx.x;
    float4 v = ((const float4*)p)[t];

    float s = v.x + v.y + v.z + v.w;
    red[t] = s; __syncthreads();
    for (int ss = 128; ss > 0; ss >>= 1) {
        if (t < ss) red[t] += red[t+ss];
        __syncthreads();
    }
    float mu = red[0] * (1.0f / (2*FEAT));
    __syncthreads();

    float d0 = v.x - mu, d1 = v.y - mu, d2 = v.z - mu, d3 = v.w - mu;
    red[t] = d0*d0 + d1*d1 + d2*d2 + d3*d3; __syncthreads();
    for (int ss = 128; ss > 0; ss >>= 1) {
        if (t < ss) red[t] += red[t+ss];
        __syncthreads();
    }
    float var = red[0] * (1.0f / (2*FEAT));
    float rs = rsqrtf(var + 1e-5f);

    int c = t << 2;
    float4 gv = *(const float4*)(g + c);
    float4 bv = *(const float4*)(bta + c);
    float y0 = d0 * rs * gv.x + bv.x;
    float y1 = d1 * rs * gv.y + bv.y;
    float y2 = d2 * rs * gv.z + bv.z;
    float y3 = d3 * rs * gv.w + bv.w;

    const float IS2 = 0.70710678118654752f;
    float4 o;
    o.x = 0.5f * y0 * (1.0f + erff(y0 * IS2));
    o.y = 0.5f * y1 * (1.0f + erff(y1 * IS2));
    o.z = 0.5f * y2 * (1.0f + erff(y2 * IS2));
    o.w = 0.5f * y3 * (1.0f + erff(y3 * IS2));
    ((float4*)(out + (size_t)blockIdx.x * (2*FEAT)))[t] = o;
}

// ---------------- host-side orchestration ----------------
static void run_block(const float* x, const float* enc,
                      const float* Wqkv, const float* bqkv,
                      const float* Wproj, const float* bproj,
                      const float* W1, const float* b1,
                      const float* ln_g, const float* ln_b,
                      const float* W2, const float* b2,
                      float* qkv, float* q, float* k, float* v,
                      float* o, float* msg, float* hh, float* gg,
                      float* outp)
{
    // qkv = x @ Wqkv + bqkv
    gemm_tf32<<<dim3(3*HIDD/128, ROWS/128), 256>>>(
        x, FEAT, nullptr, 0, 1<<30, Wqkv, 3*HIDD, bqkv, nullptr, 0,
        qkv, 3*HIDD, FEAT);

    rope_kernel<<<(Bb*Nn*Hh*(HD/2))/256, 256>>>(qkv, enc, q, k, v);

    flash_tf32<<<dim3(Nn/128, BH), 256, FLASH_SMEM_U32*4>>>(q, k, v, o);

    // message = O @ Wproj + bproj
    gemm_tf32<<<dim3(HIDD/128, ROWS/128), 256>>>(
        o, HIDD, nullptr, 0, 1<<30, Wproj, HIDD, bproj, nullptr, 0,
        msg, HIDD, HIDD);

    // h = concat(x, msg) @ W1 + b1
    gemm_tf32<<<dim3(2*FEAT/128, ROWS/128), 256>>>(
        x, FEAT, msg, HIDD, FEAT, W1, 2*FEAT, b1, nullptr, 0,
        hh, 2*FEAT, FEAT + HIDD);

    ln_gelu_kernel<<<ROWS, 256>>>(hh, ln_g, ln_b, gg);

    // out = x + g @ W2 + b2
    gemm_tf32<<<dim3(FEAT/128, ROWS/128), 256>>>(
        gg, 2*FEAT, nullptr, 0, 1<<30, W2, FEAT, b2, x, FEAT,
        outp, FEAT, 2*FEAT);
}

extern "C" void kernel_launch(void* const* d_in, const int* in_sizes, int n_in,
                              void* d_out, int out_size)
{
    const float* x0    = (const float*)d_in[0];
    const float* x1    = (const float*)d_in[1];
    const float* enc0  = (const float*)d_in[2];
    const float* enc1  = (const float*)d_in[3];
    const float* Wqkv  = (const float*)d_in[4];
    const float* bqkv  = (const float*)d_in[5];
    const float* Wproj = (const float*)d_in[6];
    const float* bproj = (const float*)d_in[7];
    const float* W1    = (const float*)d_in[8];
    const float* b1    = (const float*)d_in[9];
    const float* ln_g  = (const float*)d_in[10];
    const float* ln_b  = (const float*)d_in[11];
    const float* W2    = (const float*)d_in[12];
    const float* b2    = (const float*)d_in[13];
    float* out = (float*)d_out;

    float *qkv, *q, *k, *v, *o, *msg, *hh, *gg;
    cudaGetSymbolAddress((void**)&qkv, g_qkv);
    cudaGetSymbolAddress((void**)&q,   g_q);
    cudaGetSymbolAddress((void**)&k,   g_k);
    cudaGetSymbolAddress((void**)&v,   g_v);
    cudaGetSymbolAddress((void**)&o,   g_o);
    cudaGetSymbolAddress((void**)&msg, g_msg);
    cudaGetSymbolAddress((void**)&hh,  g_h);
    cudaGetSymbolAddress((void**)&gg,  g_g);

    cudaFuncSetAttribute(flash_tf32,
        cudaFuncAttributeMaxDynamicSharedMemorySize, FLASH_SMEM_U32*4);

    run_block(x0, enc0, Wqkv, bqkv, Wproj, bproj, W1, b1, ln_g, ln_b, W2, b2,
              qkv, q, k, v, o, msg, hh, gg, out);
    run_block(x1, enc1, Wqkv, bqkv, Wproj, bproj, W1, b1, ln_g, ln_b, W2, b2,
              qkv, q, k, v, o, msg, hh, gg, out + (size_t)ROWS*FEAT);
}

// round 4
// speedup vs baseline: 3.0458x; 1.0969x over previous
#include <cuda_runtime.h>
#include <math.h>
#include <stdint.h>

#define Bb   4
#define Nn   2048
#define FEAT 512
#define HIDD 512
#define Hh   8
#define HD   64
#define ROWS (Bb*Nn)          // 8192
#define BH   (Bb*Hh)          // 32

// ---------------- scratch (static device arrays; per-z doubled) ----------------
__device__ float g_qkv[(size_t)2*ROWS*3*HIDD];
__device__ float g_q[(size_t)2*ROWS*HIDD];    // [z][BH,N,HD], tf32 bits, q pre-scaled 1/8
__device__ float g_k[(size_t)2*ROWS*HIDD];
__device__ float g_v[(size_t)2*ROWS*HIDD];
__device__ float g_o[(size_t)2*ROWS*HIDD];    // [z][B,N,HID]
__device__ float g_msg[(size_t)2*ROWS*HIDD];
__device__ float g_h[(size_t)2*ROWS*2*FEAT];
__device__ float g_g[(size_t)2*ROWS*2*FEAT];

// ---------------- tf32 helpers ----------------
__device__ __forceinline__ uint32_t f2tf(float f) {
    uint32_t u;
    asm("cvt.rna.tf32.f32 %0, %1;" : "=r"(u) : "f"(f));
    return u;
}

__device__ __forceinline__ void mma_tf32(float* d,
    uint32_t a0, uint32_t a1, uint32_t a2, uint32_t a3,
    uint32_t b0, uint32_t b1)
{
    asm volatile(
        "mma.sync.aligned.m16n8k8.row.col.f32.tf32.tf32.f32 "
        "{%0,%1,%2,%3},{%4,%5,%6,%7},{%8,%9},{%0,%1,%2,%3};"
        : "+f"(d[0]), "+f"(d[1]), "+f"(d[2]), "+f"(d[3])
        : "r"(a0), "r"(a1), "r"(a2), "r"(a3), "r"(b0), "r"(b1));
}

// ---------------- batched tf32 GEMM over z=0,1: C = [A|A2] @ B + bias (+resid) ----------------
// 128x128 block tile, K-tile 16, 256 threads (8 warps, 4x2), warp tile 32x64.
__global__ __launch_bounds__(256, 2) void gemm_tf32(
    const float* __restrict__ A0, const float* __restrict__ A1, int lda,
    const float* __restrict__ A2_0, const float* __restrict__ A2_1, int lda2, int ksplit,
    const float* __restrict__ Bm, int ldb,
    const float* __restrict__ bias,
    const float* __restrict__ R0, const float* __restrict__ R1, int ldr,
    float* __restrict__ C, size_t zstrC, int ldc, int K)
{
    __shared__ uint32_t As[2][128*20];
    __shared__ uint32_t Bs[2][16*136];

    const int z = blockIdx.z;
    const float* A     = z ? A1   : A0;
    const float* A2    = z ? A2_1 : A2_0;
    const float* resid = z ? R1   : R0;
    float* Cz = C + (size_t)z * zstrC;

    const int t    = threadIdx.x;
    const int lane = t & 31;
    const int warp = t >> 5;
    const int wm   = warp & 3;
    const int wn   = warp >> 2;
    const int rb   = blockIdx.y * 128;
    const int cb   = blockIdx.x * 128;

    const int arow = t >> 1;
    const int ah   = (t & 1) * 8;
    const int bk   = t >> 4;
    const int bn   = (t & 15) * 4;

    const int gid  = lane >> 2;
    const int tig  = lane & 3;

    float acc[2][8][4] = {};

    float4 av0, av1, bv0, bv1;
    {
        int kg = ah;
        const float* asrc = (A2 && kg >= ksplit)
            ? A2 + (size_t)(rb + arow) * lda2 + (kg - ksplit)
            : A  + (size_t)(rb + arow) * lda  + kg;
        av0 = *(const float4*)asrc;
        av1 = *(const float4*)(asrc + 4);
        const float* bsrc = Bm + (size_t)bk * ldb + cb + bn;
        bv0 = *(const float4*)bsrc;
        bv1 = *(const float4*)(bsrc + 64);
    }
    {
        uint32_t* ap = &As[0][arow*20 + ah];
        ap[0]=f2tf(av0.x); ap[1]=f2tf(av0.y); ap[2]=f2tf(av0.z); ap[3]=f2tf(av0.w);
        ap[4]=f2tf(av1.x); ap[5]=f2tf(av1.y); ap[6]=f2tf(av1.z); ap[7]=f2tf(av1.w);
        uint32_t* bp = &Bs[0][bk*136 + bn];
        bp[0]=f2tf(bv0.x); bp[1]=f2tf(bv0.y); bp[2]=f2tf(bv0.z); bp[3]=f2tf(bv0.w);
        bp += 64;
        bp[0]=f2tf(bv1.x); bp[1]=f2tf(bv1.y); bp[2]=f2tf(bv1.z); bp[3]=f2tf(bv1.w);
    }
    __syncthreads();

    const int nk = K >> 4;
    for (int kt = 0; kt < nk; ++kt) {
        const int cur = kt & 1;
        if (kt + 1 < nk) {
            int kb = (kt + 1) << 4;
            int kg = kb + ah;
            const float* asrc = (A2 && kg >= ksplit)
                ? A2 + (size_t)(rb + arow) * lda2 + (kg - ksplit)
                : A  + (size_t)(rb + arow) * lda  + kg;
            av0 = *(const float4*)asrc;
            av1 = *(const float4*)(asrc + 4);
            const float* bsrc = Bm + (size_t)(kb + bk) * ldb + cb + bn;
            bv0 = *(const float4*)bsrc;
            bv1 = *(const float4*)(bsrc + 64);
        }

        const uint32_t* Ac = As[cur];
        const uint32_t* Bc = Bs[cur];
        #pragma unroll
        for (int ks = 0; ks < 2; ++ks) {
            uint32_t af[2][4];
            #pragma unroll
            for (int mt = 0; mt < 2; ++mt) {
                int r = wm*32 + mt*16 + gid;
                int c = ks*8 + tig;
                af[mt][0] = Ac[r*20 + c];
                af[mt][1] = Ac[(r+8)*20 + c];
                af[mt][2] = Ac[r*20 + c + 4];
                af[mt][3] = Ac[(r+8)*20 + c + 4];
            }
            #pragma unroll
            for (int nt = 0; nt < 8; ++nt) {
                int n = wn*64 + nt*8 + gid;
                int k = ks*8 + tig;
                uint32_t b0 = Bc[k*136 + n];
                uint32_t b1 = Bc[(k+4)*136 + n];
                mma_tf32(acc[0][nt], af[0][0], af[0][1], af[0][2], af[0][3], b0, b1);
                mma_tf32(acc[1][nt], af[1][0], af[1][1], af[1][2], af[1][3], b0, b1);
            }
        }

        if (kt + 1 < nk) {
            const int nxt = (kt + 1) & 1;
            uint32_t* ap = &As[nxt][arow*20 + ah];
            ap[0]=f2tf(av0.x); ap[1]=f2tf(av0.y); ap[2]=f2tf(av0.z); ap[3]=f2tf(av0.w);
            ap[4]=f2tf(av1.x); ap[5]=f2tf(av1.y); ap[6]=f2tf(av1.z); ap[7]=f2tf(av1.w);
            uint32_t* bp = &Bs[nxt][bk*136 + bn];
            bp[0]=f2tf(bv0.x); bp[1]=f2tf(bv0.y); bp[2]=f2tf(bv0.z); bp[3]=f2tf(bv0.w);
            bp += 64;
            bp[0]=f2tf(bv1.x); bp[1]=f2tf(bv1.y); bp[2]=f2tf(bv1.z); bp[3]=f2tf(bv1.w);
        }
        __syncthreads();
    }

    #pragma unroll
    for (int mt = 0; mt < 2; ++mt) {
        #pragma unroll
        for (int nt = 0; nt < 8; ++nt) {
            int row0 = rb + wm*32 + mt*16 + gid;
            int col  = cb + wn*64 + nt*8 + 2*tig;
            float2 bz = *(const float2*)(bias + col);
            float2 o0, o1;
            o0.x = acc[mt][nt][0] + bz.x;
            o0.y = acc[mt][nt][1] + bz.y;
            o1.x = acc[mt][nt][2] + bz.x;
            o1.y = acc[mt][nt][3] + bz.y;
            if (resid != nullptr) {
                float2 r0 = *(const float2*)(resid + (size_t)row0 * ldr + col);
                float2 r1 = *(const float2*)(resid + (size_t)(row0+8) * ldr + col);
                o0.x += r0.x; o0.y += r0.y;
                o1.x += r1.x; o1.y += r1.y;
            }
            *(float2*)(Cz + (size_t)row0 * ldc + col)     = o0;
            *(float2*)(Cz + (size_t)(row0+8) * ldc + col) = o1;
        }
    }
}

// ---------------- RoPE + split (batched over z); tf32-rounded; q pre-scaled 1/8 ----------------
__global__ __launch_bounds__(256) void rope_kernel(
    const float* __restrict__ qkv, const float* __restrict__ enc0,
    const float* __restrict__ enc1,
    float* __restrict__ qb, float* __restrict__ kb, float* __restrict__ vb)
{
    const int z = blockIdx.y;
    const float* enc = z ? enc1 : enc0;
    const float* qz  = qkv + (size_t)z * ROWS * 3*HIDD;
    const size_t zo  = (size_t)z * ROWS * HIDD;

    int idx = blockIdx.x * blockDim.x + threadIdx.x;
    int p  = idx & (HD/2 - 1);
    int tmp = idx >> 5;
    int h  = tmp & (Hh - 1);
    tmp >>= 3;
    int n  = tmp & (Nn - 1);
    int b  = tmp >> 11;

    size_t row  = (size_t)b * Nn + n;
    size_t base = row * (3*HIDD) + h * (HD*3) + (2*p)*3;
    float q0 = qz[base+0], k0 = qz[base+1], v0 = qz[base+2];
    float q1 = qz[base+3], k1 = qz[base+4], v1 = qz[base+5];

    size_t eb = row * HD + 2*p;
    const size_t ESTR = (size_t)Bb * Nn * HD;
    float f00 = enc[eb],      f01 = enc[eb+1];
    float f10 = enc[ESTR+eb], f11 = enc[ESTR+eb+1];

    float qo0 = (q0*f00 - q1*f10) * 0.125f;
    float qo1 = (q1*f01 + q0*f11) * 0.125f;
    float ko0 = k0*f00 - k1*f10;
    float ko1 = k1*f01 + k0*f11;

    size_t ob = zo + (((size_t)b*Hh + h) * Nn + n) * HD + 2*p;
    qb[ob]   = __uint_as_float(f2tf(qo0));
    qb[ob+1] = __uint_as_float(f2tf(qo1));
    kb[ob]   = __uint_as_float(f2tf(ko0));
    kb[ob+1] = __uint_as_float(f2tf(ko1));
    vb[ob]   = __uint_as_float(f2tf(v0));
    vb[ob+1] = __uint_as_float(f2tf(v1));
}

// ---------------- tf32 flash attention (batched over z) ----------------
#define QOFF 0
#define KOFF (128*68)
#define VOFF (KOFF + 64*68)
#define POFF (VOFF + 64*72)
#define FLASH_SMEM_U32 (POFF + 128*68)

__global__ __launch_bounds__(256, 2) void flash_tf32(
    const float* __restrict__ Q, const float* __restrict__ K,
    const float* __restrict__ V, float* __restrict__ O)
{
    extern __shared__ uint32_t smu[];
    uint32_t* Qs = smu + QOFF;
    uint32_t* Ks = smu + KOFF;
    uint32_t* Vs = smu + VOFF;
    uint32_t* Ps = smu + POFF;

    const int z  = blockIdx.z;
    const int bh = blockIdx.y;
    const int b  = bh >> 3;
    const int h  = bh & 7;
    const size_t zo = (size_t)z * ROWS * HIDD;
    const uint32_t* Qg = (const uint32_t*)(Q + zo + (size_t)bh * Nn * HD);
    const uint32_t* Kg = (const uint32_t*)(K + zo + (size_t)bh * Nn * HD);
    const uint32_t* Vg = (const uint32_t*)(V + zo + (size_t)bh * Nn * HD);
    float* Og = O + zo;

    const int t    = threadIdx.x;
    const int lane = t & 31;
    const int warp = t >> 5;
    const int gid  = lane >> 2;
    const int tig  = lane & 3;
    const int q0r  = blockIdx.x * 128;

    #pragma unroll
    for (int i = 0; i < 8; ++i) {
        int idx = t + 256*i;
        int row = idx >> 4, dq = (idx & 15) << 2;
        *(uint4*)&Qs[row*68 + dq] = *(const uint4*)&Qg[(size_t)(q0r + row)*HD + dq];
    }

    float accO[8][4] = {};
    float mrow[2] = {-1e30f, -1e30f};
    float lrow[2] = {0.f, 0.f};

    for (int j0 = 0; j0 < Nn; j0 += 64) {
        __syncthreads();
        #pragma unroll
        for (int i = 0; i < 4; ++i) {
            int idx = t + 256*i;
            int row = idx >> 4, dq = (idx & 15) << 2;
            *(uint4*)&Ks[row*68 + dq] = *(const uint4*)&Kg[(size_t)(j0 + row)*HD + dq];
            *(uint4*)&Vs[row*72 + dq] = *(const uint4*)&Vg[(size_t)(j0 + row)*HD + dq];
        }
        __syncthreads();

        float s[8][4] = {};
        #pragma unroll
        for (int ks = 0; ks < 8; ++ks) {
            int r = warp*16 + gid;
            int c = ks*8 + tig;
            uint32_t a0 = Qs[r*68 + c];
            uint32_t a1 = Qs[(r+8)*68 + c];
            uint32_t a2 = Qs[r*68 + c + 4];
            uint32_t a3 = Qs[(r+8)*68 + c + 4];
            #pragma unroll
            for (int nt = 0; nt < 8; ++nt) {
                int n = nt*8 + gid;
                int k = ks*8 + tig;
                uint32_t b0 = Ks[n*68 + k];
                uint32_t b1 = Ks[n*68 + k + 4];
                mma_tf32(s[nt], a0, a1, a2, a3, b0, b1);
            }
        }

        #pragma unroll
        for (int g = 0; g < 2; ++g) {
            float tm = -1e30f;
            #pragma unroll
            for (int nt = 0; nt < 8; ++nt)
                tm = fmaxf(tm, fmaxf(s[nt][2*g], s[nt][2*g+1]));
            tm = fmaxf(tm, __shfl_xor_sync(0xffffffffu, tm, 1));
            tm = fmaxf(tm, __shfl_xor_sync(0xffffffffu, tm, 2));
            float mn = fmaxf(mrow[g], tm);
            float alpha = __expf(mrow[g] - mn);
            mrow[g] = mn;
            float rs = 0.f;
            #pragma unroll
            for (int nt = 0; nt < 8; ++nt) {
                float p0 = __expf(s[nt][2*g]   - mn);
                float p1 = __expf(s[nt][2*g+1] - mn);
                s[nt][2*g] = p0; s[nt][2*g+1] = p1;
                rs += p0 + p1;
            }
            rs += __shfl_xor_sync(0xffffffffu, rs, 1);
            rs += __shfl_xor_sync(0xffffffffu, rs, 2);
            lrow[g] = lrow[g]*alpha + rs;
            #pragma unroll
            for (int nt = 0; nt < 8; ++nt) {
                accO[nt][2*g]   *= alpha;
                accO[nt][2*g+1] *= alpha;
            }
        }

        {
            int r0 = warp*16 + gid;
            #pragma unroll
            for (int nt = 0; nt < 8; ++nt) {
                int pc = nt*8 + 2*tig;
                Ps[r0*68 + pc]         = f2tf(s[nt][0]);
                Ps[r0*68 + pc + 1]     = f2tf(s[nt][1]);
                Ps[(r0+8)*68 + pc]     = f2tf(s[nt][2]);
                Ps[(r0+8)*68 + pc + 1] = f2tf(s[nt][3]);
            }
        }
        __syncwarp();

        #pragma unroll
        for (int ks = 0; ks < 8; ++ks) {
            int r = warp*16 + gid;
            int c = ks*8 + tig;
            uint32_t a0 = Ps[r*68 + c];
            uint32_t a1 = Ps[(r+8)*68 + c];
            uint32_t a2 = Ps[r*68 + c + 4];
            uint32_t a3 = Ps[(r+8)*68 + c + 4];
            #pragma unroll
            for (int nt = 0; nt < 8; ++nt) {
                int n = nt*8 + gid;
                int k = ks*8 + tig;
                uint32_t b0 = Vs[k*72 + n];
                uint32_t b1 = Vs[(k+4)*72 + n];
                mma_tf32(accO[nt], a0, a1, a2, a3, b0, b1);
            }
        }
    }

    #pragma unroll
    for (int g = 0; g < 2; ++g) {
        float inv = 1.0f / lrow[g];
        int n = q0r + warp*16 + gid + 8*g;
        #pragma unroll
        for (int nt = 0; nt < 8; ++nt) {
            int col = h*64 + nt*8 + 2*tig;
            float2 o;
            o.x = accO[nt][2*g]   * inv;
            o.y = accO[nt][2*g+1] * inv;
            *(float2*)&Og[((size_t)b * Nn + n) * HIDD + col] = o;
        }
    }
}

// ---------------- LayerNorm + exact GELU (batched over z) ----------------
__global__ __launch_bounds__(256) void ln_gelu_kernel(
    const float* __restrict__ H, const float* __restrict__ g,
    const float* __restrict__ bta, float* __restrict__ out)
{
    __shared__ float red[256];
    const size_t rowi = (size_t)blockIdx.y * ROWS + blockIdx.x;
    const float* p = H + rowi * (2*FEAT);
    int t = threadIdx.x;
    float4 v = ((const float4*)p)[t];

    float s = v.x + v.y + v.z + v.w;
    red[t] = s; __syncthreads();
    for (int ss = 128; ss > 0; ss >>= 1) {
        if (t < ss) red[t] += red[t+ss];
        __syncthreads();
    }
    float mu = red[0] * (1.0f / (2*FEAT));
    __syncthreads();

    float d0 = v.x - mu, d1 = v.y - mu, d2 = v.z - mu, d3 = v.w - mu;
    red[t] = d0*d0 + d1*d1 + d2*d2 + d3*d3; __syncthreads();
    for (int ss = 128; ss > 0; ss >>= 1) {
        if (t < ss) red[t] += red[t+ss];
        __syncthreads();
    }
    float var = red[0] * (1.0f / (2*FEAT));
    float rs = rsqrtf(var + 1e-5f);

    int c = t << 2;
    float4 gv = *(const float4*)(g + c);
    float4 bv = *(const float4*)(bta + c);
    float y0 = d0 * rs * gv.x + bv.x;
    float y1 = d1 * rs * gv.y + bv.y;
    float y2 = d2 * rs * gv.z + bv.z;
    float y3 = d3 * rs * gv.w + bv.w;

    const float IS2 = 0.70710678118654752f;
    float4 o;
    o.x = 0.5f * y0 * (1.0f + erff(y0 * IS2));
    o.y = 0.5f * y1 * (1.0f + erff(y1 * IS2));
    o.z = 0.5f * y2 * (1.0f + erff(y2 * IS2));
    o.w = 0.5f * y3 * (1.0f + erff(y3 * IS2));
    ((float4*)(out + rowi * (2*FEAT)))[t] = o;
}

extern "C" void kernel_launch(void* const* d_in, const int* in_sizes, int n_in,
                              void* d_out, int out_size)
{
    const float* x0    = (const float*)d_in[0];
    const float* x1    = (const float*)d_in[1];
    const float* enc0  = (const float*)d_in[2];
    const float* enc1  = (const float*)d_in[3];
    const float* Wqkv  = (const float*)d_in[4];
    const float* bqkv  = (const float*)d_in[5];
    const float* Wproj = (const float*)d_in[6];
    const float* bproj = (const float*)d_in[7];
    const float* W1    = (const float*)d_in[8];
    const float* b1    = (const float*)d_in[9];
    const float* ln_g  = (const float*)d_in[10];
    const float* ln_b  = (const float*)d_in[11];
    const float* W2    = (const float*)d_in[12];
    const float* b2    = (const float*)d_in[13];
    float* out = (float*)d_out;

    float *qkv, *q, *k, *v, *o, *msg, *hh, *gg;
    cudaGetSymbolAddress((void**)&qkv, g_qkv);
    cudaGetSymbolAddress((void**)&q,   g_q);
    cudaGetSymbolAddress((void**)&k,   g_k);
    cudaGetSymbolAddress((void**)&v,   g_v);
    cudaGetSymbolAddress((void**)&o,   g_o);
    cudaGetSymbolAddress((void**)&msg, g_msg);
    cudaGetSymbolAddress((void**)&hh,  g_h);
    cudaGetSymbolAddress((void**)&gg,  g_g);

    cudaFuncSetAttribute(flash_tf32,
        cudaFuncAttributeMaxDynamicSharedMemorySize, FLASH_SMEM_U32*4);

    const size_t ZQKV = (size_t)ROWS*3*HIDD;
    const size_t ZH   = (size_t)ROWS*HIDD;
    const size_t Z2F  = (size_t)ROWS*2*FEAT;

    // qkv = x @ Wqkv + bqkv
    gemm_tf32<<<dim3(3*HIDD/128, ROWS/128, 2), 256>>>(
        x0, x1, FEAT, nullptr, nullptr, 0, 1<<30,
        Wqkv, 3*HIDD, bqkv, nullptr, nullptr, 0,
        qkv, ZQKV, 3*HIDD, FEAT);

    rope_kernel<<<dim3((Bb*Nn*Hh*(HD/2))/256, 2), 256>>>(qkv, enc0, enc1, q, k, v);

    flash_tf32<<<dim3(Nn/128, BH, 2), 256, FLASH_SMEM_U32*4>>>(q, k, v, o);

    // message = O @ Wproj + bproj
    gemm_tf32<<<dim3(HIDD/128, ROWS/128, 2), 256>>>(
        o, o + ZH, HIDD, nullptr, nullptr, 0, 1<<30,
        Wproj, HIDD, bproj, nullptr, nullptr, 0,
        msg, ZH, HIDD, HIDD);

    // h = concat(x, msg) @ W1 + b1
    gemm_tf32<<<dim3(2*FEAT/128, ROWS/128, 2), 256>>>(
        x0, x1, FEAT, msg, msg + ZH, HIDD, FEAT,
        W1, 2*FEAT, b1, nullptr, nullptr, 0,
        hh, Z2F, 2*FEAT, FEAT + HIDD);

    ln_gelu_kernel<<<dim3(ROWS, 2), 256>>>(hh, ln_g, ln_b, gg);

    // out = x + g @ W2 + b2
    gemm_tf32<<<dim3(FEAT/128, ROWS/128, 2), 256>>>(
        gg, gg + Z2F, 2*FEAT, nullptr, nullptr, 0, 1<<30,
        W2, FEAT, b2, x0, x1, FEAT,
        out, (size_t)ROWS*FEAT, FEAT, 2*FEAT);
}